// round 7
// baseline (speedup 1.0000x reference)
#include <cuda_runtime.h>

// ---------------------------------------------------------------------------
// DeformDownsampleBlock1: full pipeline
//   residual = maxpool3d(x)
//   off1 = conv3d(x, Woff1, boff1, s=2)        -> im2col + SGEMM
//   out  = deform_conv3d(x, off1, W1, s=2)     -> sample(cols) + SGEMM
//   out  = relu(BN(out))                        (batch stats)
//   off2 = conv3d(out, Woff2, boff2, s=1)      -> im2col + SGEMM
//   out  = deform_conv3d(out, off2, W2, s=1)   -> sample(cols) + SGEMM
//   out  = BN(out) + concat(residual,residual); relu
// ---------------------------------------------------------------------------

#define N_    2
#define CIN   64
#define COUT  128
#define D1    16
#define H1    56
#define W1    56
#define P1    (D1*H1*W1)        // 50176
#define DO    8
#define HO    28
#define WO    28
#define POS   (DO*HO*WO)        // 6272
#define M_    (N_*POS)          // 12544
#define K1    (CIN*27)          // 1728
#define K2    (COUT*27)         // 3456
#define OFFC1 (8*81)            // 648
#define OFFC2 (16*81)           // 1296

// ------------------------- scratch (device globals) ------------------------
__device__ float g_xt[(size_t)N_*P1*CIN];      //  x channels-last  [n][p][c]
__device__ float g_res[(size_t)N_*CIN*POS];    //  maxpool residual [n][c][pos]
__device__ float g_colA[(size_t)K1*M_];        //  im2col1 / cols1  [k][m]
__device__ float g_colB[(size_t)K2*M_];        //  im2col2 / cols2  [k][m]
__device__ float g_off1[(size_t)OFFC1*M_];     //  [ch][m]
__device__ float g_off2[(size_t)OFFC2*M_];     //  [ch][m]
__device__ float g_o1raw[(size_t)COUT*M_];     //  conv1 out [c][m] (BN+relu in place)
__device__ float g_o1t[(size_t)M_*COUT];       //  BN+relu out channels-last [m][c]
__device__ float g_o2raw[(size_t)COUT*M_];     //  conv2 out [c][m]
__device__ float g_scale[COUT];
__device__ float g_shift[COUT];

enum { B_COLA = 0, B_COLB, B_OFF1, B_OFF2, B_O1RAW, B_O1T, B_O2RAW, B_XT };

__device__ __forceinline__ float* g_buf(int id) {
    switch (id) {
        case B_COLA:  return g_colA;
        case B_COLB:  return g_colB;
        case B_OFF1:  return g_off1;
        case B_OFF2:  return g_off2;
        case B_O1RAW: return g_o1raw;
        case B_O1T:   return g_o1t;
        case B_O2RAW: return g_o2raw;
        default:      return g_xt;
    }
}

// ----------------------- x -> channels-last transpose ----------------------
__global__ void k_transpose(const float* __restrict__ x) {
    __shared__ float s[64][65];
    int nb = blockIdx.x;                  // N_ * (P1/64) blocks
    int n  = nb / (P1 / 64);
    int p0 = (nb % (P1 / 64)) * 64;
    int t  = threadIdx.x;
    for (int i = t; i < 64 * 64; i += 256) {
        int c = i >> 6, p = i & 63;
        s[c][p] = x[((size_t)(n * CIN + c)) * P1 + p0 + p];
    }
    __syncthreads();
    for (int i = t; i < 64 * 64; i += 256) {
        int p = i >> 6, c = i & 63;
        g_xt[((size_t)(n * P1 + p0 + p)) * CIN + c] = s[c][p];
    }
}

// --------------------------------- maxpool ---------------------------------
__global__ void k_maxpool(const float* __restrict__ x) {
    int idx = blockIdx.x * 256 + threadIdx.x;
    if (idx >= N_ * CIN * POS) return;
    int pos = idx % POS;
    int c   = (idx / POS) % CIN;
    int n   = idx / (POS * CIN);
    int od = pos / (HO * WO), oh = (pos / WO) % HO, ow = pos % WO;
    const float* xp = x + ((size_t)(n * CIN + c)) * P1;
    float mx = -3.402823466e38f;
    #pragma unroll
    for (int kd = 0; kd < 3; kd++) {
        int id = od * 2 - 1 + kd;
        if (id < 0 || id >= D1) continue;
        #pragma unroll
        for (int kh = 0; kh < 3; kh++) {
            int ih = oh * 2 - 1 + kh;
            if (ih < 0 || ih >= H1) continue;
            #pragma unroll
            for (int kw = 0; kw < 3; kw++) {
                int iw = ow * 2 - 1 + kw;
                if (iw < 0 || iw >= W1) continue;
                mx = fmaxf(mx, xp[(id * H1 + ih) * W1 + iw]);
            }
        }
    }
    g_res[idx] = mx;
}

// --------------------------------- im2col ----------------------------------
// dst[k][m], k = c*27 + tap, m = n*POS + pos ; src[c*sC + n*sN + (d*H+h)*W+w]
__global__ void k_im2col(const float* __restrict__ srcExt, int srcsel, int dstsel,
                         int Dd, int Hh, int Ww, int sC, int sN, int stride,
                         int total) {
    int idx = blockIdx.x * 256 + threadIdx.x;
    if (idx >= total) return;
    const float* src = (srcsel >= 0) ? g_buf(srcsel) : srcExt;
    float* dst = g_buf(dstsel);
    int m = idx % M_;
    int k = idx / M_;
    int c = k / 27, tap = k % 27;
    int kd = tap / 9, kh = (tap / 3) % 3, kw = tap % 3;
    int n = m / POS, pos = m % POS;
    int od = pos / (HO * WO), oh = (pos / WO) % HO, ow = pos % WO;
    int id = od * stride - 1 + kd;
    int ih = oh * stride - 1 + kh;
    int iw = ow * stride - 1 + kw;
    float v = 0.f;
    if (id >= 0 && id < Dd && ih >= 0 && ih < Hh && iw >= 0 && iw < Ww)
        v = src[(size_t)c * sC + (size_t)n * sN + (id * Hh + ih) * Ww + iw];
    dst[idx] = v;
}

// ---------------------------------- SGEMM ----------------------------------
// C[co][m] = sum_k A[co][k] * B[k][m] (+ bias[co])
// BM x 128 x 8 tile, 256 threads, (BM/16) x 8 microtile, double-buffered smem.
// BM=128 for the main convs (Co=128 exact); BM=64 for offset convs (less pad).
template <int BM>
__global__ void __launch_bounds__(256) k_sgemm(const float* __restrict__ A,
                                               const float* __restrict__ bias,
                                               int bsel, int csel, int Co, int K) {
    constexpr int MI = BM / 16;       // rows per thread: 8 (BM=128) or 4 (BM=64)
    __shared__ float As[2][8][BM];    // [k][row]
    __shared__ float Bs[2][8][128];   // [k][col]
    const float* B = g_buf(bsel);
    float* C = g_buf(csel);
    int t    = threadIdx.x;
    int row0 = blockIdx.y * BM;
    int col0 = blockIdx.x * 128;
    int ty = t >> 4, tx = t & 15;      // 16x16 thread grid, MIx8 each

    // A-load mapping: first BM*2 threads each load one float4 of A
    int ar  = t >> 1;                  // 0..BM-1 (for t < BM*2)
    int akk = (t & 1) << 2;            // 0 or 4
    bool aldr = t < BM * 2;
    // B-load mapping: thread loads B[k0+bk][col0+bc .. +3]
    int bk = t >> 5;                   // 0..7
    int bc = (t & 31) << 2;            // 0..124

    float acc[MI][8];
    #pragma unroll
    for (int i = 0; i < MI; i++)
        #pragma unroll
        for (int j = 0; j < 8; j++) acc[i][j] = 0.f;

    const float* Ap = A + (size_t)(row0 + ar) * K + akk;
    const float* Bp = B + (size_t)bk * M_ + col0 + bc;
    bool arow_ok = aldr && (row0 + ar) < Co;

    int kIters = K >> 3;

    // preload iter 0 into buffer 0
    {
        float4 av = make_float4(0.f, 0.f, 0.f, 0.f);
        if (arow_ok) av = *(const float4*)(Ap);
        if (aldr) {
            As[0][akk + 0][ar] = av.x;
            As[0][akk + 1][ar] = av.y;
            As[0][akk + 2][ar] = av.z;
            As[0][akk + 3][ar] = av.w;
        }
        *(float4*)&Bs[0][bk][bc] = *(const float4*)(Bp);
    }
    __syncthreads();

    for (int it = 0; it < kIters; it++) {
        int cur = it & 1, nxt = cur ^ 1;
        float4 av, bv;
        bool have_next = (it + 1) < kIters;
        if (have_next) {
            int k0 = (it + 1) << 3;
            av = make_float4(0.f, 0.f, 0.f, 0.f);
            if (arow_ok) av = *(const float4*)(Ap + k0);
            bv = *(const float4*)(Bp + (size_t)k0 * M_);
        }
        #pragma unroll
        for (int kk = 0; kk < 8; kk++) {
            float avr[MI];
            #pragma unroll
            for (int i4 = 0; i4 < MI / 4; i4++) {
                float4 a = *(const float4*)&As[cur][kk][ty * MI + i4 * 4];
                avr[i4 * 4 + 0] = a.x;
                avr[i4 * 4 + 1] = a.y;
                avr[i4 * 4 + 2] = a.z;
                avr[i4 * 4 + 3] = a.w;
            }
            float4 b0 = *(const float4*)&Bs[cur][kk][tx * 8];
            float4 b1 = *(const float4*)&Bs[cur][kk][tx * 8 + 4];
            float bvr[8] = {b0.x, b0.y, b0.z, b0.w, b1.x, b1.y, b1.z, b1.w};
            #pragma unroll
            for (int i = 0; i < MI; i++)
                #pragma unroll
                for (int j = 0; j < 8; j++) acc[i][j] += avr[i] * bvr[j];
        }
        if (have_next) {
            if (aldr) {
                As[nxt][akk + 0][ar] = av.x;
                As[nxt][akk + 1][ar] = av.y;
                As[nxt][akk + 2][ar] = av.z;
                As[nxt][akk + 3][ar] = av.w;
            }
            *(float4*)&Bs[nxt][bk][bc] = bv;
            __syncthreads();
        }
    }

    #pragma unroll
    for (int i = 0; i < MI; i++) {
        int co = row0 + ty * MI + i;
        if (co >= Co) continue;
        float bvv = bias ? bias[co] : 0.f;
        float* Cp = C + (size_t)co * M_ + col0 + tx * 8;
        float4 o0 = make_float4(acc[i][0] + bvv, acc[i][1] + bvv,
                                acc[i][2] + bvv, acc[i][3] + bvv);
        float4 o1 = make_float4(acc[i][4] + bvv, acc[i][5] + bvv,
                                acc[i][6] + bvv, acc[i][7] + bvv);
        *(float4*)(Cp)     = o0;
        *(float4*)(Cp + 4) = o1;
    }
}

// --------------------------- deform sampling -------------------------------
// inp channels-last [n][p][CH]; off [(g*3+coord)*27+tap][m]; cols [(c*27+tap)][m]
__global__ void k_sample(int insel, int offsel, int colsel, int G, int CH,
                         int Dd, int Hh, int Ww, int stride, int total) {
    int idx = blockIdx.x * 256 + threadIdx.x;
    if (idx >= total) return;
    const float* inp  = g_buf(insel);
    const float* off  = g_buf(offsel);
    float* cols = g_buf(colsel);

    int pos = idx % POS;
    int tap = (idx / POS) % 27;
    int g   = (idx / (POS * 27)) % G;
    int n   = idx / (POS * 27 * G);
    int od = pos / (HO * WO), oh = (pos / WO) % HO, ow = pos % WO;
    int kd = tap / 9, kh = (tap / 3) % 3, kw = tap % 3;

    int ob = n * POS + pos;
    const float* offp = off + ((size_t)(g * 3) * 27 + tap) * M_ + ob;
    float pd = offp[0]                     + (float)(od * stride - 1 + kd);
    float ph = offp[(size_t)27 * M_]       + (float)(oh * stride - 1 + kh);
    float pw = offp[(size_t)2 * 27 * M_]   + (float)(ow * stride - 1 + kw);

    float d0f = floorf(pd), h0f = floorf(ph), w0f = floorf(pw);
    float fd = pd - d0f, fh = ph - h0f, fw = pw - w0f;
    int d0 = (int)d0f, h0 = (int)h0f, w0 = (int)w0f;

    float wts[8];
    int   idxs[8];
    #pragma unroll
    for (int cr = 0; cr < 8; cr++) {
        int cd = cr >> 2, ch = (cr >> 1) & 1, cw = cr & 1;
        int di = d0 + cd, hi = h0 + ch, wi = w0 + cw;
        bool v = (di >= 0) && (di < Dd) && (hi >= 0) && (hi < Hh) &&
                 (wi >= 0) && (wi < Ww);
        float wt = (cd ? fd : 1.f - fd) * (ch ? fh : 1.f - fh) *
                   (cw ? fw : 1.f - fw);
        wts[cr]  = v ? wt : 0.f;
        idxs[cr] = v ? ((di * Hh + hi) * Ww + wi) * CH : 0;
    }

    const float* base = inp + ((size_t)n * Dd * Hh * Ww) * CH + g * 8;
    float a[8];
    #pragma unroll
    for (int cc = 0; cc < 8; cc++) a[cc] = 0.f;
    #pragma unroll
    for (int cr = 0; cr < 8; cr++) {
        float wt = wts[cr];
        const float4* p = (const float4*)(base + idxs[cr]);
        float4 v0 = p[0], v1 = p[1];
        a[0] += wt * v0.x; a[1] += wt * v0.y; a[2] += wt * v0.z; a[3] += wt * v0.w;
        a[4] += wt * v1.x; a[5] += wt * v1.y; a[6] += wt * v1.z; a[7] += wt * v1.w;
    }
    float* cp = cols + ((size_t)(g * 8) * 27 + tap) * M_ + ob;
    #pragma unroll
    for (int cc = 0; cc < 8; cc++) cp[(size_t)cc * 27 * M_] = a[cc];
}

// ------------------------------- BN stats ----------------------------------
__global__ void k_bnstats(int xsel, const float* __restrict__ gam,
                          const float* __restrict__ bet) {
    int c = blockIdx.x;
    const float* p = g_buf(xsel) + (size_t)c * M_;
    float s = 0.f, s2 = 0.f;
    for (int i = threadIdx.x; i < M_; i += 256) {
        float v = p[i];
        s += v;
        s2 += v * v;
    }
    __shared__ float sh[256], sh2[256];
    sh[threadIdx.x] = s;
    sh2[threadIdx.x] = s2;
    __syncthreads();
    for (int o = 128; o > 0; o >>= 1) {
        if (threadIdx.x < o) {
            sh[threadIdx.x] += sh[threadIdx.x + o];
            sh2[threadIdx.x] += sh2[threadIdx.x + o];
        }
        __syncthreads();
    }
    if (threadIdx.x == 0) {
        float mean = sh[0] / (float)M_;
        float var  = sh2[0] / (float)M_ - mean * mean;
        float sc   = gam[c] * rsqrtf(var + 1e-5f);
        g_scale[c] = sc;
        g_shift[c] = bet[c] - mean * sc;
    }
}

// -------- BN + relu for stage 1: in place [c][m] + tiled transpose ---------
// grid (M_/32, COUT/32), 256 threads; 32x32 smem tile, both sides coalesced.
__global__ void k_bnrelu1() {
    __shared__ float s[32][33];
    int mb = blockIdx.x;                // 392 tiles over m
    int cb = blockIdx.y;                // 4 tiles over c
    int t  = threadIdx.x;
    #pragma unroll
    for (int i = t; i < 1024; i += 256) {
        int c = i >> 5, m = i & 31;     // consecutive t -> consecutive m (coalesced)
        int gc = cb * 32 + c;
        size_t gi = (size_t)gc * M_ + mb * 32 + m;
        float v = g_o1raw[gi];
        v = fmaxf(g_scale[gc] * v + g_shift[gc], 0.f);
        g_o1raw[gi] = v;
        s[c][m] = v;
    }
    __syncthreads();
    #pragma unroll
    for (int i = t; i < 1024; i += 256) {
        int m = i >> 5, c = i & 31;     // consecutive t -> consecutive c (coalesced)
        g_o1t[(size_t)(mb * 32 + m) * COUT + cb * 32 + c] = s[c][m];
    }
}

// ---------- final: BN2 + residual concat add + relu -> NCDHW out -----------
__global__ void k_final(float* __restrict__ out) {
    int idx = blockIdx.x * 256 + threadIdx.x;   // N_*COUT*POS exact
    int pos = idx % POS;
    int co  = (idx / POS) % COUT;
    int n   = idx / (POS * COUT);
    float v = g_o2raw[(size_t)co * M_ + n * POS + pos];
    v = g_scale[co] * v + g_shift[co] +
        g_res[((size_t)n * CIN + (co & 63)) * POS + pos];
    out[idx] = fmaxf(v, 0.f);
}

// ------------------------------- launcher ----------------------------------
extern "C" void kernel_launch(void* const* d_in, const int* in_sizes, int n_in,
                              void* d_out, int out_size) {
    const float* x      = (const float*)d_in[0];
    const float* w_off1 = (const float*)d_in[1];
    const float* b_off1 = (const float*)d_in[2];
    const float* w1     = (const float*)d_in[3];
    const float* g1     = (const float*)d_in[4];
    const float* be1    = (const float*)d_in[5];
    const float* w_off2 = (const float*)d_in[6];
    const float* b_off2 = (const float*)d_in[7];
    const float* w2     = (const float*)d_in[8];
    const float* g2     = (const float*)d_in[9];
    const float* be2    = (const float*)d_in[10];
    float* out = (float*)d_out;

    // stage 0: layout prep + residual
    k_transpose<<<N_ * (P1 / 64), 256>>>(x);
    k_maxpool<<<(N_ * CIN * POS + 255) / 256, 256>>>(x);

    // stage 1: offset conv1 (im2col + gemm), deform sample, gemm, BN+relu
    k_im2col<<<(K1 * M_) / 256, 256>>>(x, -1, B_COLA, D1, H1, W1,
                                       P1, CIN * P1, 2, K1 * M_);
    {
        dim3 gg(M_ / 128, (OFFC1 + 63) / 64);
        k_sgemm<64><<<gg, 256>>>(w_off1, b_off1, B_COLA, B_OFF1, OFFC1, K1);
    }
    k_sample<<<(N_ * 8 * 27 * POS + 255) / 256, 256>>>(
        B_XT, B_OFF1, B_COLA, 8, CIN, D1, H1, W1, 2, N_ * 8 * 27 * POS);
    {
        dim3 gg(M_ / 128, COUT / 128);
        k_sgemm<128><<<gg, 256>>>(w1, nullptr, B_COLA, B_O1RAW, COUT, K1);
    }
    k_bnstats<<<COUT, 256>>>(B_O1RAW, g1, be1);
    {
        dim3 gg(M_ / 32, COUT / 32);
        k_bnrelu1<<<gg, 256>>>();
    }

    // stage 2: offset conv2, deform sample, gemm, BN + residual + relu
    k_im2col<<<(K2 * M_) / 256, 256>>>(nullptr, B_O1RAW, B_COLB, DO, HO, WO,
                                       M_, POS, 1, K2 * M_);
    {
        dim3 gg(M_ / 128, (OFFC2 + 63) / 64);
        k_sgemm<64><<<gg, 256>>>(w_off2, b_off2, B_COLB, B_OFF2, OFFC2, K2);
    }
    k_sample<<<(N_ * 16 * 27 * POS + 255) / 256, 256>>>(
        B_O1T, B_OFF2, B_COLB, 16, COUT, DO, HO, WO, 1, N_ * 16 * 27 * POS);
    {
        dim3 gg(M_ / 128, COUT / 128);
        k_sgemm<128><<<gg, 256>>>(w2, nullptr, B_COLB, B_O2RAW, COUT, K2);
    }
    k_bnstats<<<COUT, 256>>>(B_O2RAW, g2, be2);
    k_final<<<(N_ * COUT * POS) / 256, 256>>>(out);
}

// round 9
// speedup vs baseline: 1.3950x; 1.3950x over previous
#include <cuda_runtime.h>

// ---------------------------------------------------------------------------
// DeformDownsampleBlock1: full pipeline
//   residual = maxpool3d(x)
//   off1 = conv3d(x, Woff1, boff1, s=2)        -> im2col + SGEMM
//   out  = deform_conv3d(x, off1, W1, s=2)     -> sample(cols) + SGEMM
//   out  = relu(BN(out))                        (batch stats)
//   off2 = conv3d(out, Woff2, boff2, s=1)      -> im2col + SGEMM
//   out  = deform_conv3d(out, off2, W2, s=1)   -> sample(cols) + SGEMM
//   out  = BN(out) + concat(residual,residual); relu
// ---------------------------------------------------------------------------

#define N_    2
#define CIN   64
#define COUT  128
#define D1    16
#define H1    56
#define W1    56
#define P1    (D1*H1*W1)        // 50176
#define DO    8
#define HO    28
#define WO    28
#define POS   (DO*HO*WO)        // 6272
#define M_    (N_*POS)          // 12544
#define K1    (CIN*27)          // 1728
#define K2    (COUT*27)         // 3456
#define OFFC1 (8*81)            // 648
#define OFFC2 (16*81)           // 1296

// ------------------------- scratch (device globals) ------------------------
__device__ float g_xt[(size_t)N_*P1*CIN];      //  x channels-last  [n][p][c]
__device__ float g_res[(size_t)N_*CIN*POS];    //  maxpool residual [n][c][pos]
__device__ float g_colA[(size_t)K1*M_];        //  im2col1 / cols1  [k][m]
__device__ float g_colB[(size_t)K2*M_];        //  im2col2 / cols2  [k][m]
__device__ float g_off1[(size_t)OFFC1*M_];     //  [ch][m]
__device__ float g_off2[(size_t)OFFC2*M_];     //  [ch][m]
__device__ float g_o1raw[(size_t)COUT*M_];     //  conv1 out [c][m] (BN+relu in place)
__device__ float g_o1t[(size_t)M_*COUT];       //  BN+relu out channels-last [m][c]
__device__ float g_o2raw[(size_t)COUT*M_];     //  conv2 out [c][m]
__device__ float g_scale[COUT];
__device__ float g_shift[COUT];

enum { B_COLA = 0, B_COLB, B_OFF1, B_OFF2, B_O1RAW, B_O1T, B_O2RAW, B_XT };

__device__ __forceinline__ float* g_buf(int id) {
    switch (id) {
        case B_COLA:  return g_colA;
        case B_COLB:  return g_colB;
        case B_OFF1:  return g_off1;
        case B_OFF2:  return g_off2;
        case B_O1RAW: return g_o1raw;
        case B_O1T:   return g_o1t;
        case B_O2RAW: return g_o2raw;
        default:      return g_xt;
    }
}

// ----------------------- x -> channels-last transpose ----------------------
__global__ void k_transpose(const float* __restrict__ x) {
    __shared__ float s[64][65];
    int nb = blockIdx.x;                  // N_ * (P1/64) blocks
    int n  = nb / (P1 / 64);
    int p0 = (nb % (P1 / 64)) * 64;
    int t  = threadIdx.x;
    for (int i = t; i < 64 * 64; i += 256) {
        int c = i >> 6, p = i & 63;
        s[c][p] = x[((size_t)(n * CIN + c)) * P1 + p0 + p];
    }
    __syncthreads();
    for (int i = t; i < 64 * 64; i += 256) {
        int p = i >> 6, c = i & 63;
        g_xt[((size_t)(n * P1 + p0 + p)) * CIN + c] = s[c][p];
    }
}

// --------------------------------- maxpool ---------------------------------
__global__ void k_maxpool(const float* __restrict__ x) {
    int idx = blockIdx.x * 256 + threadIdx.x;
    if (idx >= N_ * CIN * POS) return;
    int pos = idx % POS;
    int c   = (idx / POS) % CIN;
    int n   = idx / (POS * CIN);
    int od = pos / (HO * WO), oh = (pos / WO) % HO, ow = pos % WO;
    const float* xp = x + ((size_t)(n * CIN + c)) * P1;
    float mx = -3.402823466e38f;
    #pragma unroll
    for (int kd = 0; kd < 3; kd++) {
        int id = od * 2 - 1 + kd;
        if (id < 0 || id >= D1) continue;
        #pragma unroll
        for (int kh = 0; kh < 3; kh++) {
            int ih = oh * 2 - 1 + kh;
            if (ih < 0 || ih >= H1) continue;
            #pragma unroll
            for (int kw = 0; kw < 3; kw++) {
                int iw = ow * 2 - 1 + kw;
                if (iw < 0 || iw >= W1) continue;
                mx = fmaxf(mx, xp[(id * H1 + ih) * W1 + iw]);
            }
        }
    }
    g_res[idx] = mx;
}

// --------------------------------- im2col ----------------------------------
// dst[k][m], k = c*27 + tap, m = n*POS + pos ; src[c*sC + n*sN + (d*H+h)*W+w]
__global__ void k_im2col(const float* __restrict__ srcExt, int srcsel, int dstsel,
                         int Dd, int Hh, int Ww, int sC, int sN, int stride,
                         int total) {
    int idx = blockIdx.x * 256 + threadIdx.x;
    if (idx >= total) return;
    const float* src = (srcsel >= 0) ? g_buf(srcsel) : srcExt;
    float* dst = g_buf(dstsel);
    int m = idx % M_;
    int k = idx / M_;
    int c = k / 27, tap = k % 27;
    int kd = tap / 9, kh = (tap / 3) % 3, kw = tap % 3;
    int n = m / POS, pos = m % POS;
    int od = pos / (HO * WO), oh = (pos / WO) % HO, ow = pos % WO;
    int id = od * stride - 1 + kd;
    int ih = oh * stride - 1 + kh;
    int iw = ow * stride - 1 + kw;
    float v = 0.f;
    if (id >= 0 && id < Dd && ih >= 0 && ih < Hh && iw >= 0 && iw < Ww)
        v = src[(size_t)c * sC + (size_t)n * sN + (id * Hh + ih) * Ww + iw];
    dst[idx] = v;
}

// ---------------------------------- SGEMM ----------------------------------
// C[co][m] = sum_k A[co][k] * B[k][m] (+ bias[co])
// BM x 128 x 8 tile, 256 threads, double-buffered smem.
// Split-group microtile: thread owns cols {tx*4..+3} and {64+tx*4..+3},
// rows {ty*4..+3} (+{64+ty*4..+3} when BM=128) -> conflict-free LDS.128.
template <int BM>
__global__ void __launch_bounds__(256) k_sgemm(const float* __restrict__ A,
                                               const float* __restrict__ bias,
                                               int bsel, int csel, int Co, int K) {
    constexpr int IG = BM / 64;       // row groups per thread: 2 (BM=128) / 1 (BM=64)
    __shared__ float As[2][8][BM];    // [k][row]
    __shared__ float Bs[2][8][128];   // [k][col]
    const float* B = g_buf(bsel);
    float* C = g_buf(csel);
    int t    = threadIdx.x;
    int row0 = blockIdx.y * BM;
    int col0 = blockIdx.x * 128;
    int ty = t >> 4, tx = t & 15;      // 16x16 thread grid

    // A-load mapping: first BM*2 threads each load one float4 of A
    int ar  = t >> 1;                  // 0..BM-1 (for t < BM*2)
    int akk = (t & 1) << 2;            // 0 or 4
    bool aldr = t < BM * 2;
    // B-load mapping: thread loads B[k0+bk][col0+bc .. +3]
    int bk = t >> 5;                   // 0..7
    int bc = (t & 31) << 2;            // 0..124

    float acc[IG * 4][8];
    #pragma unroll
    for (int i = 0; i < IG * 4; i++)
        #pragma unroll
        for (int j = 0; j < 8; j++) acc[i][j] = 0.f;

    const float* Ap = A + (size_t)(row0 + ar) * K + akk;
    const float* Bp = B + (size_t)bk * M_ + col0 + bc;
    bool arow_ok = aldr && (row0 + ar) < Co;

    int kIters = K >> 3;

    // preload iter 0 into buffer 0
    {
        float4 av = make_float4(0.f, 0.f, 0.f, 0.f);
        if (arow_ok) av = *(const float4*)(Ap);
        if (aldr) {
            As[0][akk + 0][ar] = av.x;
            As[0][akk + 1][ar] = av.y;
            As[0][akk + 2][ar] = av.z;
            As[0][akk + 3][ar] = av.w;
        }
        *(float4*)&Bs[0][bk][bc] = *(const float4*)(Bp);
    }
    __syncthreads();

    for (int it = 0; it < kIters; it++) {
        int cur = it & 1, nxt = cur ^ 1;
        float4 av, bv;
        bool have_next = (it + 1) < kIters;
        if (have_next) {
            int k0 = (it + 1) << 3;
            av = make_float4(0.f, 0.f, 0.f, 0.f);
            if (arow_ok) av = *(const float4*)(Ap + k0);
            bv = *(const float4*)(Bp + (size_t)k0 * M_);
        }
        #pragma unroll
        for (int kk = 0; kk < 8; kk++) {
            float avr[IG * 4];
            #pragma unroll
            for (int ig = 0; ig < IG; ig++) {
                float4 a = *(const float4*)&As[cur][kk][ig * 64 + ty * 4];
                avr[ig * 4 + 0] = a.x;
                avr[ig * 4 + 1] = a.y;
                avr[ig * 4 + 2] = a.z;
                avr[ig * 4 + 3] = a.w;
            }
            float4 b0 = *(const float4*)&Bs[cur][kk][tx * 4];
            float4 b1 = *(const float4*)&Bs[cur][kk][64 + tx * 4];
            float bvr[8] = {b0.x, b0.y, b0.z, b0.w, b1.x, b1.y, b1.z, b1.w};
            #pragma unroll
            for (int i = 0; i < IG * 4; i++)
                #pragma unroll
                for (int j = 0; j < 8; j++) acc[i][j] += avr[i] * bvr[j];
        }
        if (have_next) {
            if (aldr) {
                As[nxt][akk + 0][ar] = av.x;
                As[nxt][akk + 1][ar] = av.y;
                As[nxt][akk + 2][ar] = av.z;
                As[nxt][akk + 3][ar] = av.w;
            }
            *(float4*)&Bs[nxt][bk][bc] = bv;
            __syncthreads();
        }
    }

    #pragma unroll
    for (int ig = 0; ig < IG; ig++) {
        #pragma unroll
        for (int ii = 0; ii < 4; ii++) {
            int i  = ig * 4 + ii;
            int co = row0 + ig * 64 + ty * 4 + ii;
            if (co >= Co) continue;
            float bvv = bias ? bias[co] : 0.f;
            float* Cp = C + (size_t)co * M_ + col0;
            float4 o0 = make_float4(acc[i][0] + bvv, acc[i][1] + bvv,
                                    acc[i][2] + bvv, acc[i][3] + bvv);
            float4 o1 = make_float4(acc[i][4] + bvv, acc[i][5] + bvv,
                                    acc[i][6] + bvv, acc[i][7] + bvv);
            *(float4*)(Cp + tx * 4)      = o0;
            *(float4*)(Cp + 64 + tx * 4) = o1;
        }
    }
}

// --------------------------- deform sampling -------------------------------
// inp channels-last [n][p][CH]; off [(g*3+coord)*27+tap][m]; cols [(c*27+tap)][m]
__global__ void k_sample(int insel, int offsel, int colsel, int G, int CH,
                         int Dd, int Hh, int Ww, int stride, int total) {
    int idx = blockIdx.x * 256 + threadIdx.x;
    if (idx >= total) return;
    const float* inp  = g_buf(insel);
    const float* off  = g_buf(offsel);
    float* cols = g_buf(colsel);

    int pos = idx % POS;
    int tap = (idx / POS) % 27;
    int g   = (idx / (POS * 27)) % G;
    int n   = idx / (POS * 27 * G);
    int od = pos / (HO * WO), oh = (pos / WO) % HO, ow = pos % WO;
    int kd = tap / 9, kh = (tap / 3) % 3, kw = tap % 3;

    int ob = n * POS + pos;
    const float* offp = off + ((size_t)(g * 3) * 27 + tap) * M_ + ob;
    float pd = offp[0]                     + (float)(od * stride - 1 + kd);
    float ph = offp[(size_t)27 * M_]       + (float)(oh * stride - 1 + kh);
    float pw = offp[(size_t)2 * 27 * M_]   + (float)(ow * stride - 1 + kw);

    float d0f = floorf(pd), h0f = floorf(ph), w0f = floorf(pw);
    float fd = pd - d0f, fh = ph - h0f, fw = pw - w0f;
    int d0 = (int)d0f, h0 = (int)h0f, w0 = (int)w0f;

    float wts[8];
    int   idxs[8];
    #pragma unroll
    for (int cr = 0; cr < 8; cr++) {
        int cd = cr >> 2, ch = (cr >> 1) & 1, cw = cr & 1;
        int di = d0 + cd, hi = h0 + ch, wi = w0 + cw;
        bool v = (di >= 0) && (di < Dd) && (hi >= 0) && (hi < Hh) &&
                 (wi >= 0) && (wi < Ww);
        float wt = (cd ? fd : 1.f - fd) * (ch ? fh : 1.f - fh) *
                   (cw ? fw : 1.f - fw);
        wts[cr]  = v ? wt : 0.f;
        idxs[cr] = v ? ((di * Hh + hi) * Ww + wi) * CH : 0;
    }

    const float* base = inp + ((size_t)n * Dd * Hh * Ww) * CH + g * 8;
    float a[8];
    #pragma unroll
    for (int cc = 0; cc < 8; cc++) a[cc] = 0.f;
    #pragma unroll
    for (int cr = 0; cr < 8; cr++) {
        float wt = wts[cr];
        const float4* p = (const float4*)(base + idxs[cr]);
        float4 v0 = p[0], v1 = p[1];
        a[0] += wt * v0.x; a[1] += wt * v0.y; a[2] += wt * v0.z; a[3] += wt * v0.w;
        a[4] += wt * v1.x; a[5] += wt * v1.y; a[6] += wt * v1.z; a[7] += wt * v1.w;
    }
    float* cp = cols + ((size_t)(g * 8) * 27 + tap) * M_ + ob;
    #pragma unroll
    for (int cc = 0; cc < 8; cc++) cp[(size_t)cc * 27 * M_] = a[cc];
}

// ------------------------------- BN stats ----------------------------------
__global__ void k_bnstats(int xsel, const float* __restrict__ gam,
                          const float* __restrict__ bet) {
    int c = blockIdx.x;
    const float* p = g_buf(xsel) + (size_t)c * M_;
    float s = 0.f, s2 = 0.f;
    for (int i = threadIdx.x; i < M_; i += 256) {
        float v = p[i];
        s += v;
        s2 += v * v;
    }
    __shared__ float sh[256], sh2[256];
    sh[threadIdx.x] = s;
    sh2[threadIdx.x] = s2;
    __syncthreads();
    for (int o = 128; o > 0; o >>= 1) {
        if (threadIdx.x < o) {
            sh[threadIdx.x] += sh[threadIdx.x + o];
            sh2[threadIdx.x] += sh2[threadIdx.x + o];
        }
        __syncthreads();
    }
    if (threadIdx.x == 0) {
        float mean = sh[0] / (float)M_;
        float var  = sh2[0] / (float)M_ - mean * mean;
        float sc   = gam[c] * rsqrtf(var + 1e-5f);
        g_scale[c] = sc;
        g_shift[c] = bet[c] - mean * sc;
    }
}

// -------- BN + relu for stage 1: in place [c][m] + tiled transpose ---------
// grid (M_/32, COUT/32), 256 threads; 32x32 smem tile, both sides coalesced.
__global__ void k_bnrelu1() {
    __shared__ float s[32][33];
    int mb = blockIdx.x;                // 392 tiles over m
    int cb = blockIdx.y;                // 4 tiles over c
    int t  = threadIdx.x;
    #pragma unroll
    for (int i = t; i < 1024; i += 256) {
        int c = i >> 5, m = i & 31;     // consecutive t -> consecutive m (coalesced)
        int gc = cb * 32 + c;
        size_t gi = (size_t)gc * M_ + mb * 32 + m;
        float v = g_o1raw[gi];
        v = fmaxf(g_scale[gc] * v + g_shift[gc], 0.f);
        g_o1raw[gi] = v;
        s[c][m] = v;
    }
    __syncthreads();
    #pragma unroll
    for (int i = t; i < 1024; i += 256) {
        int m = i >> 5, c = i & 31;     // consecutive t -> consecutive c (coalesced)
        g_o1t[(size_t)(mb * 32 + m) * COUT + cb * 32 + c] = s[c][m];
    }
}

// ---------- final: BN2 + residual concat add + relu -> NCDHW out -----------
__global__ void k_final(float* __restrict__ out) {
    int idx = blockIdx.x * 256 + threadIdx.x;   // N_*COUT*POS exact
    int pos = idx % POS;
    int co  = (idx / POS) % COUT;
    int n   = idx / (POS * COUT);
    float v = g_o2raw[(size_t)co * M_ + n * POS + pos];
    v = g_scale[co] * v + g_shift[co] +
        g_res[((size_t)n * CIN + (co & 63)) * POS + pos];
    out[idx] = fmaxf(v, 0.f);
}

// ------------------------------- launcher ----------------------------------
extern "C" void kernel_launch(void* const* d_in, const int* in_sizes, int n_in,
                              void* d_out, int out_size) {
    const float* x      = (const float*)d_in[0];
    const float* w_off1 = (const float*)d_in[1];
    const float* b_off1 = (const float*)d_in[2];
    const float* w1     = (const float*)d_in[3];
    const float* g1     = (const float*)d_in[4];
    const float* be1    = (const float*)d_in[5];
    const float* w_off2 = (const float*)d_in[6];
    const float* b_off2 = (const float*)d_in[7];
    const float* w2     = (const float*)d_in[8];
    const float* g2     = (const float*)d_in[9];
    const float* be2    = (const float*)d_in[10];
    float* out = (float*)d_out;

    // stage 0: layout prep + residual
    k_transpose<<<N_ * (P1 / 64), 256>>>(x);
    k_maxpool<<<(N_ * CIN * POS + 255) / 256, 256>>>(x);

    // stage 1: offset conv1 (im2col + gemm), deform sample, gemm, BN+relu
    k_im2col<<<(K1 * M_) / 256, 256>>>(x, -1, B_COLA, D1, H1, W1,
                                       P1, CIN * P1, 2, K1 * M_);
    {
        dim3 gg(M_ / 128, (OFFC1 + 63) / 64);
        k_sgemm<64><<<gg, 256>>>(w_off1, b_off1, B_COLA, B_OFF1, OFFC1, K1);
    }
    k_sample<<<(N_ * 8 * 27 * POS + 255) / 256, 256>>>(
        B_XT, B_OFF1, B_COLA, 8, CIN, D1, H1, W1, 2, N_ * 8 * 27 * POS);
    {
        dim3 gg(M_ / 128, COUT / 128);
        k_sgemm<128><<<gg, 256>>>(w1, nullptr, B_COLA, B_O1RAW, COUT, K1);
    }
    k_bnstats<<<COUT, 256>>>(B_O1RAW, g1, be1);
    {
        dim3 gg(M_ / 32, COUT / 32);
        k_bnrelu1<<<gg, 256>>>();
    }

    // stage 2: offset conv2, deform sample, gemm, BN + residual + relu
    k_im2col<<<(K2 * M_) / 256, 256>>>(nullptr, B_O1RAW, B_COLB, DO, HO, WO,
                                       M_, POS, 1, K2 * M_);
    {
        dim3 gg(M_ / 128, (OFFC2 + 127) / 128);
        k_sgemm<128><<<gg, 256>>>(w_off2, b_off2, B_COLB, B_OFF2, OFFC2, K2);
    }
    k_sample<<<(N_ * 16 * 27 * POS + 255) / 256, 256>>>(
        B_O1T, B_OFF2, B_COLB, 16, COUT, DO, HO, WO, 1, N_ * 16 * 27 * POS);
    {
        dim3 gg(M_ / 128, COUT / 128);
        k_sgemm<128><<<gg, 256>>>(w2, nullptr, B_COLB, B_O2RAW, COUT, K2);
    }
    k_bnstats<<<COUT, 256>>>(B_O2RAW, g2, be2);
    k_final<<<(N_ * COUT * POS) / 256, 256>>>(out);
}